// round 6
// baseline (speedup 1.0000x reference)
#include <cuda_runtime.h>
#include <cstdint>

// 2-layer LSTM, H=6, F=6, B=4096, T=1024.
// 2 batch elements per warp (16-lane segments) -> 2048 warps for latency hiding.
// Within a segment, lane j = k + 6p (k<6, p in {0,1}) owns TWO gate rows of
// hidden index k for BOTH layers, packed f32x2 (lo=layer0, hi=layer1):
//   p=0: gates {i, g};  p=1: gates {f, o}.
// Cell update on p=1 lanes after one cross-shuffle of the packed i*g product.
// h state broadcast as packed (h0,h1) 64-bit shuffles (no re-pack movs).
// Software-pipelined: iteration t computes layer0(t+1) and layer1(t).
// Activations: tanh.approx; sigmoid = 0.5*tanh(z/2)+0.5, 0.5 folded into weights.

#define WARPS_PER_BLOCK 4
#define THREADS (WARPS_PER_BLOCK * 32)
#define ELEMS_PER_WARP 2
#define T_LEN 1024
#define TCHUNK 32
#define NCHUNK (T_LEN / TCHUNK)
#define CSTRIDE 200                 // padded per-element smem stride (floats)
#define CSTRIDE4 (CSTRIDE / 4)

typedef unsigned long long ull;

__device__ __forceinline__ float tanha(float x) {
    float y; asm("tanh.approx.f32 %0, %1;" : "=f"(y) : "f"(x)); return y;
}
__device__ __forceinline__ ull pk2(float lo, float hi) {
    ull r; asm("mov.b64 %0, {%1, %2};" : "=l"(r) : "f"(lo), "f"(hi)); return r;
}
__device__ __forceinline__ void upk2(float& lo, float& hi, ull v) {
    asm("mov.b64 {%0, %1}, %2;" : "=f"(lo), "=f"(hi) : "l"(v));
}
__device__ __forceinline__ ull fma2(ull a, ull b, ull c) {
    ull d; asm("fma.rn.f32x2 %0, %1, %2, %3;" : "=l"(d) : "l"(a), "l"(b), "l"(c));
    return d;
}

__global__ __launch_bounds__(THREADS, 1)
void lstm2_kernel(const float* __restrict__ x,
                  const float* __restrict__ wih0, const float* __restrict__ whh0,
                  const float* __restrict__ bih0, const float* __restrict__ bhh0,
                  const float* __restrict__ wih1, const float* __restrict__ whh1,
                  const float* __restrict__ bih1, const float* __restrict__ bhh1,
                  float* __restrict__ out)
{
    __shared__ float sx[2][WARPS_PER_BLOCK][ELEMS_PER_WARP * CSTRIDE];
    __shared__ float so[WARPS_PER_BLOCK][ELEMS_PER_WARP * CSTRIDE];

    const int lane = threadIdx.x & 31;
    const int warp = threadIdx.x >> 5;
    const int e    = lane >> 4;                       // element within warp
    const int s    = lane & 15;                       // lane within segment
    const int p    = (s >= 6 && s < 12) ? 1 : 0;      // gate-pair owner
    const int k    = (s < 6) ? s : ((s < 12) ? s - 6 : 0);
    const int srcm = (s >= 6) ? (s - 6) : s;          // i*g gather source

    const int b0 = (blockIdx.x * WARPS_PER_BLOCK + warp) * ELEMS_PER_WARP;

    // Gate rows: p=0 -> A=i(k), B=g(12+k);  p=1 -> A=f(6+k), B=o(18+k)
    const int rowA = p ? (6 + k) : k;
    const int rowB = p ? (18 + k) : (12 + k);
    const float scB = p ? 0.5f : 1.0f;   // weight pre-scale for gate B
    const float cmB = p ? 0.5f : 1.0f;   // activation transform for gate B
    const float cbB = p ? 0.5f : 0.0f;

    ull wxA[6], whA[6], wxB[6], whB[6];
#pragma unroll
    for (int q = 0; q < 6; q++) {
        wxA[q] = pk2(wih0[rowA * 6 + q] * 0.5f, wih1[rowA * 6 + q] * 0.5f);
        whA[q] = pk2(whh0[rowA * 6 + q] * 0.5f, whh1[rowA * 6 + q] * 0.5f);
        wxB[q] = pk2(wih0[rowB * 6 + q] * scB,  wih1[rowB * 6 + q] * scB);
        whB[q] = pk2(whh0[rowB * 6 + q] * scB,  whh1[rowB * 6 + q] * scB);
    }
    const ull bA = pk2((bih0[rowA] + bhh0[rowA]) * 0.5f,
                       (bih1[rowA] + bhh1[rowA]) * 0.5f);
    const ull bB = pk2((bih0[rowB] + bhh0[rowB]) * scB,
                       (bih1[rowB] + bhh1[rowB]) * scB);

    ull rec[6];                      // per-q packed (h0, h1)
    float c0g = 0.0f, c1g = 0.0f;    // layer0/layer1 cells (valid on p=1 lanes)

    auto stage = [&](int c, int buf) {
        float4* dst = reinterpret_cast<float4*>(sx[buf][warp]);
#pragma unroll
        for (int i = 0; i < 3; i++) {                // 96 float4 per warp
            int idx = i * 32 + lane;
            int ee  = idx / 48;
            int off = idx - ee * 48;
            const float4* src = reinterpret_cast<const float4*>(
                x + (size_t)(b0 + ee) * (T_LEN * 6) + c * (TCHUNK * 6));
            dst[ee * CSTRIDE4 + off] = src[off];
        }
    };

    // ---- prologue: stage chunk 0; layer0 at t=0 (h0=0, c0=0) ----
    stage(0, 0);
    __syncwarp();
    {
        const float* xr = &sx[0][warp][e * CSTRIDE];
        ull zA = bA, zB = bB;
#pragma unroll
        for (int q = 0; q < 6; q++) {
            const ull inp = pk2(xr[q], 0.0f);
            zA = fma2(wxA[q], inp, zA);
            zB = fma2(wxB[q], inp, zB);
        }
        float a0, a1, b0f, b1f;
        upk2(a0, a1, zA); upk2(b0f, b1f, zB);
        const float vA0 = fmaf(0.5f, tanha(a0), 0.5f);
        const float vB0 = fmaf(cmB, tanha(b0f), cbB);
        (void)a1; (void)b1f;
        const float m0 = vA0 * vB0;                       // p0: i*g
        const ull mp = pk2(m0, 0.0f);
        const ull mr = __shfl_sync(0xffffffffu, mp, srcm, 16);
        float mr0, mr1; upk2(mr0, mr1, mr); (void)mr1;
        c0g = mr0;                                        // c0 = i*g  (c was 0)
        const float h0n = vB0 * tanha(c0g);               // p1: o * tanh(c0)
        c1g = 0.0f;
        const ull hpair = pk2(h0n, 0.0f);
#pragma unroll
        for (int q = 0; q < 6; q++)
            rec[q] = __shfl_sync(0xffffffffu, hpair, 6 + q, 16);
    }

    // ---- main loop: iteration t computes layer0(t+1) and layer1(t) ----
    for (int c = 0; c < NCHUNK; c++) {
        if (c + 1 < NCHUNK) stage(c + 1, (c + 1) & 1);
        __syncwarp();

        const float* bcur = sx[c & 1][warp] + e * CSTRIDE;
        const float* bnxt = sx[(c + 1) & 1][warp] + e * CSTRIDE;

#pragma unroll 4
        for (int dt = 0; dt < TCHUNK; dt++) {
            const float* xr = (dt < TCHUNK - 1) ? (bcur + (dt + 1) * 6) : bnxt;

            ull zA = bA, zB = bB;
#pragma unroll
            for (int q = 0; q < 6; q++) {
                float h0q, h1q; upk2(h0q, h1q, rec[q]); (void)h1q;
                const ull inp = pk2(xr[q], h0q);   // (x(t+1), h0(t))
                zA = fma2(wxA[q], inp, zA);
                zA = fma2(whA[q], rec[q], zA);
                zB = fma2(wxB[q], inp, zB);
                zB = fma2(whB[q], rec[q], zB);
            }

            float a0, a1, b0f, b1f;
            upk2(a0, a1, zA); upk2(b0f, b1f, zB);
            const float vA0 = fmaf(0.5f, tanha(a0), 0.5f);   // i (p0) / f (p1), L0
            const float vA1 = fmaf(0.5f, tanha(a1), 0.5f);   // L1
            const float vB0 = fmaf(cmB, tanha(b0f), cbB);    // g (p0) / o (p1), L0
            const float vB1 = fmaf(cmB, tanha(b1f), cbB);    // L1

            const ull mp = pk2(vA0 * vB0, vA1 * vB1);        // p0 lanes: (i*g)_L0, _L1
            const ull mr = __shfl_sync(0xffffffffu, mp, srcm, 16);
            float mr0, mr1; upk2(mr0, mr1, mr);

            c0g = fmaf(vA0, c0g, mr0);                       // p1: f*c + i*g
            c1g = fmaf(vA1, c1g, mr1);
            const float h0n = vB0 * tanha(c0g);              // p1: o * tanh(c)
            const float h1n = vB1 * tanha(c1g);

            if (p) so[warp][e * CSTRIDE + dt * 6 + k] = h1n;

            const ull hpair = pk2(h0n, h1n);
#pragma unroll
            for (int q = 0; q < 6; q++)
                rec[q] = __shfl_sync(0xffffffffu, hpair, 6 + q, 16);
        }
        __syncwarp();

        // ---- flush output chunk (96 float4 per warp) ----
        {
            const float4* src = reinterpret_cast<const float4*>(so[warp]);
#pragma unroll
            for (int i = 0; i < 3; i++) {
                int idx = i * 32 + lane;
                int ee  = idx / 48;
                int off = idx - ee * 48;
                float4* dst = reinterpret_cast<float4*>(
                    out + (size_t)(b0 + ee) * (T_LEN * 6) + c * (TCHUNK * 6));
                dst[off] = src[ee * CSTRIDE4 + off];
            }
        }
        __syncwarp();
    }
}

extern "C" void kernel_launch(void* const* d_in, const int* in_sizes, int n_in,
                              void* d_out, int out_size)
{
    const float* x    = (const float*)d_in[0];
    const float* wih0 = (const float*)d_in[1];
    const float* whh0 = (const float*)d_in[2];
    const float* bih0 = (const float*)d_in[3];
    const float* bhh0 = (const float*)d_in[4];
    const float* wih1 = (const float*)d_in[5];
    const float* whh1 = (const float*)d_in[6];
    const float* bih1 = (const float*)d_in[7];
    const float* bhh1 = (const float*)d_in[8];
    float* out = (float*)d_out;

    const int B = in_sizes[0] / (T_LEN * 6);                   // 4096
    const int grid = B / (WARPS_PER_BLOCK * ELEMS_PER_WARP);   // 512

    lstm2_kernel<<<grid, THREADS>>>(x, wih0, whh0, bih0, bhh0,
                                    wih1, whh1, bih1, bhh1, out);
}

// round 7
// speedup vs baseline: 1.1562x; 1.1562x over previous
#include <cuda_runtime.h>
#include <cstdint>

// 2-layer LSTM, H=6, F=6, B=4096, T=1024.
// R5 layout (best known): 4 batch elements per warp; lane k (k<6) of each
// 8-lane segment owns hidden index k, computing all four gate rows (i,f,g,o)
// for BOTH layers packed f32x2 (lo=layer0, hi=layer1). Cell chain lane-local.
// This revision: split 12-deep fma2 chains into 2x6 + add2, packed (h0,h1)
// recurrent state end-to-end (no re-pack movs), register-prefetched x row.
// Software-pipelined: iteration t computes layer0(t+1) and layer1(t).
// Activations: tanh.approx; sigmoid = 0.5*tanh(z/2)+0.5, 0.5 folded into weights.

#define WARPS_PER_BLOCK 4
#define THREADS (WARPS_PER_BLOCK * 32)
#define ELEMS_PER_WARP 4
#define T_LEN 1024
#define TCHUNK 32
#define NCHUNK (T_LEN / TCHUNK)
#define CSTRIDE 200                 // padded per-element smem stride (floats)
#define CSTRIDE4 (CSTRIDE / 4)

typedef unsigned long long ull;

__device__ __forceinline__ float tanha(float x) {
    float y; asm("tanh.approx.f32 %0, %1;" : "=f"(y) : "f"(x)); return y;
}
__device__ __forceinline__ ull pk2(float lo, float hi) {
    ull r; asm("mov.b64 %0, {%1, %2};" : "=l"(r) : "f"(lo), "f"(hi)); return r;
}
__device__ __forceinline__ void upk2(float& lo, float& hi, ull v) {
    asm("mov.b64 {%0, %1}, %2;" : "=f"(lo), "=f"(hi) : "l"(v));
}
__device__ __forceinline__ float lo2(ull v) {
    float lo, hi; asm("mov.b64 {%0, %1}, %2;" : "=f"(lo), "=f"(hi) : "l"(v));
    return lo;
}
__device__ __forceinline__ ull fma2(ull a, ull b, ull c) {
    ull d; asm("fma.rn.f32x2 %0, %1, %2, %3;" : "=l"(d) : "l"(a), "l"(b), "l"(c));
    return d;
}
__device__ __forceinline__ ull add2(ull a, ull b) {
    ull d; asm("add.rn.f32x2 %0, %1, %2;" : "=l"(d) : "l"(a), "l"(b));
    return d;
}

__global__ __launch_bounds__(THREADS, 1)
void lstm2_kernel(const float* __restrict__ x,
                  const float* __restrict__ wih0, const float* __restrict__ whh0,
                  const float* __restrict__ bih0, const float* __restrict__ bhh0,
                  const float* __restrict__ wih1, const float* __restrict__ whh1,
                  const float* __restrict__ bih1, const float* __restrict__ bhh1,
                  float* __restrict__ out)
{
    __shared__ float sx[2][WARPS_PER_BLOCK][ELEMS_PER_WARP * CSTRIDE];
    __shared__ float so[WARPS_PER_BLOCK][ELEMS_PER_WARP * CSTRIDE];

    const int lane = threadIdx.x & 31;
    const int warp = threadIdx.x >> 5;
    const int e    = lane >> 3;
    const int s    = lane & 7;
    const int k    = (s < 6) ? s : 0;

    const int b0 = (blockIdx.x * WARPS_PER_BLOCK + warp) * ELEMS_PER_WARP;

    // Packed weights: lo = layer0 row, hi = layer1 row.
    // Sigmoid rows (i,f,o) pre-scaled by 0.5 (sigmoid-via-tanh); g rows unscaled.
    ull wxp[4][6], whp[4][6], bp[4];
#pragma unroll
    for (int g = 0; g < 4; g++) {
        const float sc = (g == 2) ? 1.0f : 0.5f;
        const int row = g * 6 + k;
#pragma unroll
        for (int q = 0; q < 6; q++) {
            wxp[g][q] = pk2(wih0[row * 6 + q] * sc, wih1[row * 6 + q] * sc);
            whp[g][q] = pk2(whh0[row * 6 + q] * sc, whh1[row * 6 + q] * sc);
        }
        bp[g] = pk2((bih0[row] + bhh0[row]) * sc, (bih1[row] + bhh1[row]) * sc);
    }

    ull rec[6];          // packed (h0[q], h1[q])
    float c0 = 0.0f, c1 = 0.0f;

    auto stage = [&](int c, int buf) {
        float4* dst = reinterpret_cast<float4*>(sx[buf][warp]);
#pragma unroll
        for (int i = 0; i < 6; i++) {
            int idx = i * 32 + lane;
            int ee  = idx / 48;
            int off = idx - ee * 48;
            const float4* src = reinterpret_cast<const float4*>(
                x + (size_t)(b0 + ee) * (T_LEN * 6) + c * (TCHUNK * 6));
            dst[ee * CSTRIDE4 + off] = src[off];
        }
    };

    // ---- prologue: stage chunk 0; layer0 at t=0 (h0=0, c0=0) ----
    stage(0, 0);
    __syncwarp();
    {
        const float* xr = &sx[0][warp][e * CSTRIDE];
        ull z[4];
#pragma unroll
        for (int g = 0; g < 4; g++) z[g] = bp[g];
#pragma unroll
        for (int q = 0; q < 6; q++) {
            const ull inp = pk2(xr[q], 0.0f);
#pragma unroll
            for (int g = 0; g < 4; g++) z[g] = fma2(wxp[g][q], inp, z[g]);
        }
        const float i0 = fmaf(0.5f, tanha(lo2(z[0])), 0.5f);
        const float g0 = tanha(lo2(z[2]));
        const float o0 = fmaf(0.5f, tanha(lo2(z[3])), 0.5f);
        c0 = i0 * g0;
        const float h = o0 * tanha(c0);
        const ull hpair = pk2(h, 0.0f);
#pragma unroll
        for (int q = 0; q < 6; q++)
            rec[q] = __shfl_sync(0xffffffffu, hpair, q, 8);
    }

    // ---- main loop: iteration t computes layer0(t+1) and layer1(t) ----
    for (int c = 0; c < NCHUNK; c++) {
        if (c + 1 < NCHUNK) stage(c + 1, (c + 1) & 1);
        __syncwarp();

        const float* bcur = sx[c & 1][warp] + e * CSTRIDE;
        const float* bnxt = sx[(c + 1) & 1][warp] + e * CSTRIDE;

#pragma unroll 4
        for (int dt = 0; dt < TCHUNK; dt++) {
            const float* xrp = (dt < TCHUNK - 1) ? (bcur + (dt + 1) * 6) : bnxt;
            // prefetch 6 x floats via three aligned 8-byte loads
            float xv[6];
            {
                const float2* x2 = reinterpret_cast<const float2*>(xrp);
                float2 a = x2[0], bq = x2[1], cc = x2[2];
                xv[0] = a.x;  xv[1] = a.y;
                xv[2] = bq.x; xv[3] = bq.y;
                xv[4] = cc.x; xv[5] = cc.y;
            }

            // split accumulation: qlo = q 0..2 (seeded with bias), qhi = q 3..5
            ull zl[4], zh[4];
#pragma unroll
            for (int g = 0; g < 4; g++) { zl[g] = bp[g]; zh[g] = 0; }
#pragma unroll
            for (int q = 0; q < 3; q++) {
                const ull inp = pk2(xv[q], lo2(rec[q]));   // (x(t+1), h0(t))
#pragma unroll
                for (int g = 0; g < 4; g++) {
                    zl[g] = fma2(wxp[g][q], inp, zl[g]);
                    zl[g] = fma2(whp[g][q], rec[q], zl[g]);
                }
            }
#pragma unroll
            for (int q = 3; q < 6; q++) {
                const ull inp = pk2(xv[q], lo2(rec[q]));
#pragma unroll
                for (int g = 0; g < 4; g++) {
                    zh[g] = fma2(wxp[g][q], inp, zh[g]);
                    zh[g] = fma2(whp[g][q], rec[q], zh[g]);
                }
            }

            float zi0, zi1, zf0, zf1, zg0, zg1, zo0, zo1;
            upk2(zi0, zi1, add2(zl[0], zh[0]));
            upk2(zf0, zf1, add2(zl[1], zh[1]));
            upk2(zg0, zg1, add2(zl[2], zh[2]));
            upk2(zo0, zo1, add2(zl[3], zh[3]));

            const float i0 = fmaf(0.5f, tanha(zi0), 0.5f);
            const float f0 = fmaf(0.5f, tanha(zf0), 0.5f);
            const float g0 = tanha(zg0);
            const float o0 = fmaf(0.5f, tanha(zo0), 0.5f);
            const float i1 = fmaf(0.5f, tanha(zi1), 0.5f);
            const float f1 = fmaf(0.5f, tanha(zf1), 0.5f);
            const float g1 = tanha(zg1);
            const float o1 = fmaf(0.5f, tanha(zo1), 0.5f);

            c0 = fmaf(f0, c0, i0 * g0);
            c1 = fmaf(f1, c1, i1 * g1);
            const float h0n = o0 * tanha(c0);
            const float h1n = o1 * tanha(c1);

            if (s < 6) so[warp][e * CSTRIDE + dt * 6 + s] = h1n;

            const ull hpair = pk2(h0n, h1n);
#pragma unroll
            for (int q = 0; q < 6; q++)
                rec[q] = __shfl_sync(0xffffffffu, hpair, q, 8);
        }
        __syncwarp();

        // ---- flush output chunk ----
        {
            const float4* src = reinterpret_cast<const float4*>(so[warp]);
#pragma unroll
            for (int i = 0; i < 6; i++) {
                int idx = i * 32 + lane;
                int ee  = idx / 48;
                int off = idx - ee * 48;
                float4* dst = reinterpret_cast<float4*>(
                    out + (size_t)(b0 + ee) * (T_LEN * 6) + c * (TCHUNK * 6));
                dst[off] = src[ee * CSTRIDE4 + off];
            }
        }
        __syncwarp();
    }
}

extern "C" void kernel_launch(void* const* d_in, const int* in_sizes, int n_in,
                              void* d_out, int out_size)
{
    const float* x    = (const float*)d_in[0];
    const float* wih0 = (const float*)d_in[1];
    const float* whh0 = (const float*)d_in[2];
    const float* bih0 = (const float*)d_in[3];
    const float* bhh0 = (const float*)d_in[4];
    const float* wih1 = (const float*)d_in[5];
    const float* whh1 = (const float*)d_in[6];
    const float* bih1 = (const float*)d_in[7];
    const float* bhh1 = (const float*)d_in[8];
    float* out = (float*)d_out;

    const int B = in_sizes[0] / (T_LEN * 6);                   // 4096
    const int grid = B / (WARPS_PER_BLOCK * ELEMS_PER_WARP);   // 256

    lstm2_kernel<<<grid, THREADS>>>(x, wih0, whh0, bih0, bhh0,
                                    wih1, whh1, bih1, bhh1, out);
}